// round 16
// baseline (speedup 1.0000x reference)
#include <cuda_runtime.h>
#include <cuda_bf16.h>
#include <math.h>
#include <stdint.h>

// ---------------------------------------------------------------------------
// BDH forward. GEMMs = bf16 hi/lo 3-combo merged-pass HMMA, cp.async 2-stage
// pipeline, 128x128 tiles, wave-balanced split-K grids, fused attention tail,
// vectorized weight transposes, score-diagonal fill dedup, bf16-pair x buffer.
// B=2,T=256,D=256,H=4,n=8192,N=32768,V=32000,L=6
// ---------------------------------------------------------------------------
#define LAYERS 6
#define LN_EPS 1e-5f
#define SCALE_ATTN 0.011048543456039806f   // 1/sqrt(8192)

#define ROWE 40                  // smem row stride in bf16 elements (80 bytes)
#define TILE_E (128 * ROWE)      // 5120 bf16 per tile
#define BUF_E  (4 * TILE_E)      // 4 tiles per buffer
#define SMEM_BYTES (2 * BUF_E * 2)   // 81920 B

#define SPLITS2 12               // scores split-K (256 chunks -> 21/22 each)
#define SPLITS3 36               // enc split-K (1024 chunks -> 28/29 each)

__device__ __forceinline__ uint32_t smem_u32(const void* p) {
    uint32_t a;
    asm("{ .reg .u64 t; cvta.to.shared.u64 t, %1; cvt.u32.u64 %0, t; }"
        : "=r"(a) : "l"(p));
    return a;
}
#define CP16(dst, src) \
    asm volatile("cp.async.cg.shared.global [%0], [%1], 16;" \
        :: "r"(dst), "l"(src) : "memory")
#define CP_COMMIT() asm volatile("cp.async.commit_group;" ::: "memory")
#define CP_WAIT(n)  asm volatile("cp.async.wait_group %0;" :: "n"(n) : "memory")

__device__ __forceinline__ void mma16816(float d[4], const uint32_t a[4],
                                         uint32_t b0, uint32_t b1) {
    asm volatile(
        "mma.sync.aligned.m16n8k16.row.col.f32.bf16.bf16.f32 "
        "{%0,%1,%2,%3}, {%4,%5,%6,%7}, {%8,%9}, {%0,%1,%2,%3};"
        : "+f"(d[0]), "+f"(d[1]), "+f"(d[2]), "+f"(d[3])
        : "r"(a[0]), "r"(a[1]), "r"(a[2]), "r"(a[3]), "r"(b0), "r"(b1));
}

// ------------------------- device globals ----------------------------------
__device__ float g_v[512*256];
__device__ float g_cos[256*4096];
__device__ float g_sin[256*4096];
__device__ __align__(16) float g_sparts[(size_t)SPLITS2*8*256*256];
__device__ __align__(16) float g_kparts[(size_t)SPLITS3*512*256];

__device__ __align__(16) __nv_bfloat16 v_h[512*256],   v_l[512*256];
__device__ __align__(16) __nv_bfloat16 lna_h[512*256], lna_l[512*256];
__device__ __align__(16) __nv_bfloat16 x_h[(size_t)8*256*8192];   // relu(dec-x)
__device__ __align__(16) __nv_bfloat16 x_l[(size_t)8*256*8192];
__device__ __align__(16) __nv_bfloat16 xr_h[(size_t)8*256*8192];
__device__ __align__(16) __nv_bfloat16 xr_l[(size_t)8*256*8192];
__device__ __align__(16) __nv_bfloat16 y_h[(size_t)512*32768];
__device__ __align__(16) __nv_bfloat16 y_l[(size_t)512*32768];
__device__ __align__(16) __nv_bfloat16 dxt_h[(size_t)32768*256];
__device__ __align__(16) __nv_bfloat16 dxt_l[(size_t)32768*256];
__device__ __align__(16) __nv_bfloat16 dyt_h[(size_t)32768*256];
__device__ __align__(16) __nv_bfloat16 dyt_l[(size_t)32768*256];
__device__ __align__(16) __nv_bfloat16 et_h[(size_t)256*32768];
__device__ __align__(16) __nv_bfloat16 et_l[(size_t)256*32768];
__device__ __align__(16) __nv_bfloat16 rt_h[(size_t)32000*256];
__device__ __align__(16) __nv_bfloat16 rt_l[(size_t)32000*256];

__device__ __forceinline__ void bf16split(float v, __nv_bfloat16& h, __nv_bfloat16& l) {
    h = __float2bfloat16(v);
    l = __float2bfloat16(v - __bfloat162float(h));
}

// ------------------------- block reductions --------------------------------
__device__ __forceinline__ float blk_sum256(float v, float* sh) {
#pragma unroll
    for (int o = 16; o > 0; o >>= 1) v += __shfl_xor_sync(0xffffffffu, v, o);
    if ((threadIdx.x & 31) == 0) sh[threadIdx.x >> 5] = v;
    __syncthreads();
    float tot = 0.f;
#pragma unroll
    for (int w = 0; w < 8; w++) tot += sh[w];
    __syncthreads();
    return tot;
}
__device__ __forceinline__ float blk_max256(float v, float* sh) {
#pragma unroll
    for (int o = 16; o > 0; o >>= 1) v = fmaxf(v, __shfl_xor_sync(0xffffffffu, v, o));
    if ((threadIdx.x & 31) == 0) sh[threadIdx.x >> 5] = v;
    __syncthreads();
    float tot = -3.0e38f;
#pragma unroll
    for (int w = 0; w < 8; w++) tot = fmaxf(tot, sh[w]);
    __syncthreads();
    return tot;
}
__device__ __forceinline__ float ln_elem(float x, float* sh) {
    float mean = blk_sum256(x, sh) * (1.f / 256.f);
    float d = x - mean;
    float var = blk_sum256(d * d, sh) * (1.f / 256.f);
    return d * rsqrtf(var + LN_EPS);
}

// ------------------------- small kernels -----------------------------------
__global__ void k_rope_table() {
    int idx = blockIdx.x * 256 + threadIdx.x;
    int i = idx & 4095;
    int t = idx >> 12;
    float ex = (float)(2 * i) * (1.0f / 8192.0f);
    float inv = expf(-9.210340371976184f * ex);
    float f = (float)t * inv;
    float s, c;
    sincosf(f, &s, &c);
    g_cos[idx] = c;
    g_sin[idx] = s;
}

__global__ void k_embed(const int* __restrict__ idx, const float* __restrict__ wte) {
    __shared__ float sh[8];
    int row = blockIdx.x, tid = threadIdx.x;
    int tok = idx[row];
    float x = wte[(size_t)tok * 256 + tid];
    float r = ln_elem(x, sh);
    g_v[row * 256 + tid] = r;
    __nv_bfloat16 h, l; bf16split(r, h, l);
    v_h[row * 256 + tid] = h; v_l[row * 256 + tid] = l;
}

// transpose + bf16 hi/lo: out[c*R + r] = in[r*C + c]; DST selected in-kernel.
template<int DST>
__global__ void k_tcvt(const float* __restrict__ in, int R, int C,
                       size_t in_z, size_t out_z) {
    __shared__ float tile[32][33];
    __nv_bfloat16* oh;
    __nv_bfloat16* ol;
    if (DST == 0) { oh = dxt_h; ol = dxt_l; }
    else if (DST == 1) { oh = dyt_h; ol = dyt_l; }
    else if (DST == 2) { oh = et_h; ol = et_l; }
    else { oh = rt_h; ol = rt_l; }
    int z = blockIdx.z;
    const float* src = in + (size_t)z * in_z;
    __nv_bfloat16* dh = oh + (size_t)z * out_z;
    __nv_bfloat16* dl = ol + (size_t)z * out_z;
    int r0 = blockIdx.y * 32, c0 = blockIdx.x * 32;
    int t = threadIdx.x;
    {
        int row = t >> 3, c4 = (t & 7) << 2;
        float4 v = *reinterpret_cast<const float4*>(
            src + (size_t)(r0 + row) * C + c0 + c4);
        tile[row][c4 + 0] = v.x; tile[row][c4 + 1] = v.y;
        tile[row][c4 + 2] = v.z; tile[row][c4 + 3] = v.w;
    }
    __syncthreads();
    {
        int ci = t >> 3, rp = (t & 7) << 2;
        float f0 = tile[rp + 0][ci], f1 = tile[rp + 1][ci];
        float f2 = tile[rp + 2][ci], f3 = tile[rp + 3][ci];
        __nv_bfloat16 h0, l0, h1, l1, h2, l2, h3, l3;
        bf16split(f0, h0, l0); bf16split(f1, h1, l1);
        bf16split(f2, h2, l2); bf16split(f3, h3, l3);
        size_t o = (size_t)(c0 + ci) * R + r0 + rp;
        *reinterpret_cast<__nv_bfloat162*>(&dh[o])     = __nv_bfloat162(h0, h1);
        *reinterpret_cast<__nv_bfloat162*>(&dh[o + 2]) = __nv_bfloat162(h2, h3);
        *reinterpret_cast<__nv_bfloat162*>(&dl[o])     = __nv_bfloat162(l0, l1);
        *reinterpret_cast<__nv_bfloat162*>(&dl[o + 2]) = __nv_bfloat162(l2, l3);
    }
}

// fused attention tail: softmax (mean over heads) + P@V + LN -> lna hi/lo
__global__ void k_attn() {
    __shared__ float sh[8];
    __shared__ float p[256];
    int row = blockIdx.x;
    int b = row >> 8, t = row & 255;
    int s = threadIdx.x;
    float pacc = 0.f;
    for (int h = 0; h < 4; h++) {
        float val = -3.0e38f;
        if (s <= t) {
            float sum = 0.f;
            int bh = b * 4 + h;
#pragma unroll
            for (int sp = 0; sp < SPLITS2; sp++)
                sum += g_sparts[(((size_t)sp * 8 + bh) * 256 + t) * 256 + s];
            val = sum * SCALE_ATTN;
        }
        float mx = blk_max256(val, sh);
        float e = (s <= t) ? expf(val - mx) : 0.f;
        float ssum = blk_sum256(e, sh);
        pacc += e / ssum;
    }
    p[s] = pacc * 0.25f;
    __syncthreads();
    const float* vb = g_v + (size_t)b * 65536;
    float a = 0.f;
#pragma unroll 8
    for (int s2 = 0; s2 < 256; s2++)
        a = fmaf(p[s2], vb[s2 * 256 + s], a);
    float r = ln_elem(a, sh);
    __nv_bfloat16 h, l; bf16split(r, h, l);
    lna_h[row * 256 + s] = h; lna_l[row * 256 + s] = l;
}

// fused: z = sum of SPLITS3 split-K partials; v = ln(v + ln(z))
__global__ void k_residual() {
    __shared__ float sh[8];
    int row = blockIdx.x, tid = threadIdx.x;
    int i = row * 256 + tid;
    float z = 0.f;
#pragma unroll
    for (int sp = 0; sp < SPLITS3; sp++) z += g_kparts[(size_t)sp * 131072 + i];
    float lnz = ln_elem(z, sh);
    float t = g_v[i] + lnz;
    float r = ln_elem(t, sh);
    g_v[i] = r;
    __nv_bfloat16 h, l; bf16split(r, h, l);
    v_h[i] = h; v_l[i] = l;
}

// ------------------------- HMMA GEMM (merged, cp.async 2-stage) -------------
// MODE: 0=dec-x (relu -> x hi/lo + fused rope -> xr hi/lo)
//       1=dec-y (relu * x -> y hi/lo)
//       2=scores (fp32 -> g_sparts, 12 uneven splits; diag tiles reuse A fills)
//       3=enc (fp32 -> g_kparts, 36 uneven splits)   4=readout (fp32 -> out)
// 128x128 tile, BK=32 (2 k-steps), 8 warps (2m x 4n), warp tile 64x32.
// Per chunk: Ah,Al,Bh,Bl tiles via cp.async; cfr += Ah*Bh + Ah*Bl + Al*Bh.
template<int MODE>
__global__ void __launch_bounds__(256, 2) k_mma(float* __restrict__ outp) {
    extern __shared__ __align__(16) __nv_bfloat16 smem_dyn[];
    const uint32_t sbase = smem_u32(smem_dyn);

    int tid = threadIdx.x;
    int wid = tid >> 5, lane = tid & 31;
    int warp_m = wid & 1, warp_n = wid >> 1;
    int gid = lane >> 2, tig = lane & 3;

    const __nv_bfloat16 *Ah, *Al, *Bh, *Bl;
    size_t K;
    int m0, n0, k0, total;
    if (MODE == 0) {
        Ah = v_h; Al = v_l; Bh = dxt_h; Bl = dxt_l;
        K = 256; m0 = blockIdx.y << 7; n0 = blockIdx.x << 7; k0 = 0; total = 8;
    } else if (MODE == 1) {
        Ah = lna_h; Al = lna_l; Bh = dyt_h; Bl = dyt_l;
        K = 256; m0 = blockIdx.y << 7; n0 = blockIdx.x << 7; k0 = 0; total = 8;
    } else if (MODE == 2) {
        size_t off = (size_t)blockIdx.y * 256 * 8192;
        Ah = xr_h + off; Al = xr_l + off; Bh = Ah; Bl = Al;
        K = 8192;
        int tp = blockIdx.x;
        m0 = ((tp + 1) >> 1) << 7; n0 = (tp >> 1) << 7;
        int s = blockIdx.z;                         // 12 uneven splits of 256 chunks
        total = 21 + (s < 4);
        k0 = (21 * s + min(s, 4)) << 5;
    } else if (MODE == 3) {
        Ah = y_h; Al = y_l; Bh = et_h; Bl = et_l;
        K = 32768; m0 = blockIdx.y << 7; n0 = blockIdx.x << 7;
        int s = blockIdx.z;                         // 36 uneven splits of 1024 chunks
        total = 28 + (s < 16);
        k0 = (28 * s + min(s, 16)) << 5;
    } else {
        Ah = v_h; Al = v_l; Bh = rt_h; Bl = rt_l;
        K = 256; m0 = blockIdx.y << 7; n0 = blockIdx.x << 7; k0 = 0; total = 8;
    }

    // score diagonal tiles: B data == A data; skip B fills, alias smem
    const bool diag = (MODE == 2) && (m0 == n0);

    // per-thread fill geometry: rows r and r+64, 16B column chunk c16
    const int r = tid >> 2, c16 = tid & 3;
    const uint32_t dOff0 = (uint32_t)(r * ROWE + c16 * 8) * 2;          // bytes
    const uint32_t dOff1 = (uint32_t)((r + 64) * ROWE + c16 * 8) * 2;

#define CPA_CHUNK(c) do {                                                     \
        int _kk = k0 + ((c) << 5);                                            \
        uint32_t _b = sbase + ((c) & 1) * (BUF_E * 2);                        \
        const size_t _ao0 = (size_t)(m0 + r) * K + _kk + c16 * 8;            \
        const size_t _ao1 = (size_t)(m0 + r + 64) * K + _kk + c16 * 8;       \
        CP16(_b + dOff0, Ah + _ao0);                                          \
        CP16(_b + dOff1, Ah + _ao1);                                          \
        CP16(_b + TILE_E * 2 + dOff0, Al + _ao0);                             \
        CP16(_b + TILE_E * 2 + dOff1, Al + _ao1);                             \
        if (!diag) {                                                          \
            const size_t _bo0 = (size_t)(n0 + r) * K + _kk + c16 * 8;        \
            const size_t _bo1 = (size_t)(n0 + r + 64) * K + _kk + c16 * 8;   \
            CP16(_b + TILE_E * 4 + dOff0, Bh + _bo0);                         \
            CP16(_b + TILE_E * 4 + dOff1, Bh + _bo1);                         \
            CP16(_b + TILE_E * 6 + dOff0, Bl + _bo0);                         \
            CP16(_b + TILE_E * 6 + dOff1, Bl + _bo1);                         \
        }                                                                     \
    } while (0)

    float cfr[4][4][4] = {};            // [mi][ng][reg]

    CPA_CHUNK(0); CP_COMMIT();
    if (total > 1) { CPA_CHUNK(1); CP_COMMIT(); }

    for (int c = 0; c < total; c++) {
        if (c + 1 < total) CP_WAIT(1); else CP_WAIT(0);
        __syncthreads();

        const __nv_bfloat16* sAh = smem_dyn + (c & 1) * BUF_E;
        const __nv_bfloat16* sAl = sAh + TILE_E;
        const __nv_bfloat16* sBh = diag ? sAh : (sAl + TILE_E);
        const __nv_bfloat16* sBl = diag ? sAl : (sAl + 2 * TILE_E);
#pragma unroll
        for (int ks = 0; ks < 2; ks++) {
            const int kc = ks * 16 + tig * 2;
            uint32_t af[4][4];
            uint32_t b0[4], b1[4];
            // --- A-hi fragments ---
#pragma unroll
            for (int mi = 0; mi < 4; mi++) {
                int ar = warp_m * 64 + mi * 16 + gid;
                af[mi][0] = *reinterpret_cast<const uint32_t*>(&sAh[ar * ROWE + kc]);
                af[mi][1] = *reinterpret_cast<const uint32_t*>(&sAh[(ar + 8) * ROWE + kc]);
                af[mi][2] = *reinterpret_cast<const uint32_t*>(&sAh[ar * ROWE + kc + 8]);
                af[mi][3] = *reinterpret_cast<const uint32_t*>(&sAh[(ar + 8) * ROWE + kc + 8]);
            }
            // --- combo hi*hi ---
#pragma unroll
            for (int ng = 0; ng < 4; ng++) {
                int br = warp_n * 32 + ng * 8 + gid;
                b0[ng] = *reinterpret_cast<const uint32_t*>(&sBh[br * ROWE + kc]);
                b1[ng] = *reinterpret_cast<const uint32_t*>(&sBh[br * ROWE + kc + 8]);
            }
#pragma unroll
            for (int mi = 0; mi < 4; mi++)
#pragma unroll
                for (int ng = 0; ng < 4; ng++)
                    mma16816(cfr[mi][ng], af[mi], b0[ng], b1[ng]);
            // --- combo hi*lo ---
#pragma unroll
            for (int ng = 0; ng < 4; ng++) {
                int br = warp_n * 32 + ng * 8 + gid;
                b0[ng] = *reinterpret_cast<const uint32_t*>(&sBl[br * ROWE + kc]);
                b1[ng] = *reinterpret_cast<const uint32_t*>(&sBl[br * ROWE + kc + 8]);
            }
#pragma unroll
            for (int mi = 0; mi < 4; mi++)
#pragma unroll
                for (int ng = 0; ng < 4; ng++)
                    mma16816(cfr[mi][ng], af[mi], b0[ng], b1[ng]);
            // --- combo lo*hi ---
#pragma unroll
            for (int mi = 0; mi < 4; mi++) {
                int ar = warp_m * 64 + mi * 16 + gid;
                af[mi][0] = *reinterpret_cast<const uint32_t*>(&sAl[ar * ROWE + kc]);
                af[mi][1] = *reinterpret_cast<const uint32_t*>(&sAl[(ar + 8) * ROWE + kc]);
                af[mi][2] = *reinterpret_cast<const uint32_t*>(&sAl[ar * ROWE + kc + 8]);
                af[mi][3] = *reinterpret_cast<const uint32_t*>(&sAl[(ar + 8) * ROWE + kc + 8]);
            }
#pragma unroll
            for (int ng = 0; ng < 4; ng++) {
                int br = warp_n * 32 + ng * 8 + gid;
                b0[ng] = *reinterpret_cast<const uint32_t*>(&sBh[br * ROWE + kc]);
                b1[ng] = *reinterpret_cast<const uint32_t*>(&sBh[br * ROWE + kc + 8]);
            }
#pragma unroll
            for (int mi = 0; mi < 4; mi++)
#pragma unroll
                for (int ng = 0; ng < 4; ng++)
                    mma16816(cfr[mi][ng], af[mi], b0[ng], b1[ng]);
        }
        __syncthreads();                 // all warps done with buf (c&1)
        if (c + 2 < total) { CPA_CHUNK(c + 2); CP_COMMIT(); }
    }
#undef CPA_CHUNK

    // ---- epilogue (scalar stores only) ----
#pragma unroll
    for (int mi = 0; mi < 4; mi++) {
#pragma unroll
        for (int hh = 0; hh < 2; hh++) {
            int row = m0 + warp_m * 64 + mi * 16 + gid + hh * 8;
#pragma unroll
            for (int ng = 0; ng < 4; ng++) {
                int col = n0 + warp_n * 32 + ng * 8 + tig * 2;
                float v0 = cfr[mi][ng][hh * 2 + 0];
                float v1 = cfr[mi][ng][hh * 2 + 1];
                if (MODE == 0) {
                    int b = row >> 8, t = row & 255;
                    int hd = col >> 13, i = col & 8191;
                    size_t xi = ((size_t)((b << 2) + hd) * 256 + t) * 8192 + i;
                    float xe = fmaxf(v0, 0.f), xo = fmaxf(v1, 0.f);
                    __nv_bfloat16 xh0, xl0, xh1, xl1;
                    bf16split(xe, xh0, xl0); bf16split(xo, xh1, xl1);
                    x_h[xi] = xh0; x_h[xi + 1] = xh1;
                    x_l[xi] = xl0; x_l[xi + 1] = xl1;
                    int ci = t * 4096 + (i >> 1);
                    float cc = g_cos[ci], ss = g_sin[ci];
                    float re = xe * cc - xo * ss;
                    float ro = xo * cc + xe * ss;
                    __nv_bfloat16 h0, l0, h1, l1;
                    bf16split(re, h0, l0); bf16split(ro, h1, l1);
                    xr_h[xi] = h0; xr_h[xi + 1] = h1;
                    xr_l[xi] = l0; xr_l[xi + 1] = l1;
                } else if (MODE == 1) {
                    int b = row >> 8, t = row & 255;
                    int hd = col >> 13, i = col & 8191;
                    size_t xi = ((size_t)((b << 2) + hd) * 256 + t) * 8192 + i;
                    float xv0 = __bfloat162float(x_h[xi]) + __bfloat162float(x_l[xi]);
                    float xv1 = __bfloat162float(x_h[xi + 1]) + __bfloat162float(x_l[xi + 1]);
                    float y0 = fmaxf(v0, 0.f) * xv0;
                    float y1 = fmaxf(v1, 0.f) * xv1;
                    size_t yi = (size_t)row * 32768 + col;
                    __nv_bfloat16 h0, l0, h1, l1;
                    bf16split(y0, h0, l0); bf16split(y1, h1, l1);
                    y_h[yi] = h0; y_h[yi + 1] = h1;
                    y_l[yi] = l0; y_l[yi + 1] = l1;
                } else if (MODE == 2) {
                    size_t ob = (((size_t)blockIdx.z * 8 + blockIdx.y) * 256 + row) * 256 + col;
                    g_sparts[ob] = v0; g_sparts[ob + 1] = v1;
                } else if (MODE == 3) {
                    size_t ob = ((size_t)blockIdx.z * 512 + row) * 256 + col;
                    g_kparts[ob] = v0; g_kparts[ob + 1] = v1;
                } else {
                    size_t ob = (size_t)row * 32000 + col;
                    outp[ob] = v0; outp[ob + 1] = v1;
                }
            }
        }
    }
}

// ------------------------- host launcher -----------------------------------
extern "C" void kernel_launch(void* const* d_in, const int* in_sizes, int n_in,
                              void* d_out, int out_size) {
    const int*   idx  = (const int*)d_in[0];
    const float* wte  = (const float*)d_in[1];
    const float* enc  = (const float*)d_in[2];
    const float* decx = (const float*)d_in[3];
    const float* decy = (const float*)d_in[4];
    const float* ro   = (const float*)d_in[5];
    float* out = (float*)d_out;
    (void)in_sizes; (void)n_in; (void)out_size;

    cudaFuncSetAttribute(k_mma<0>, cudaFuncAttributeMaxDynamicSharedMemorySize, SMEM_BYTES);
    cudaFuncSetAttribute(k_mma<1>, cudaFuncAttributeMaxDynamicSharedMemorySize, SMEM_BYTES);
    cudaFuncSetAttribute(k_mma<2>, cudaFuncAttributeMaxDynamicSharedMemorySize, SMEM_BYTES);
    cudaFuncSetAttribute(k_mma<3>, cudaFuncAttributeMaxDynamicSharedMemorySize, SMEM_BYTES);
    cudaFuncSetAttribute(k_mma<4>, cudaFuncAttributeMaxDynamicSharedMemorySize, SMEM_BYTES);

    k_rope_table<<<4096, 256>>>();
    k_embed<<<512, 256>>>(idx, wte);
    k_tcvt<0><<<dim3(256, 8, 4), 256>>>(decx, 256, 8192,
                                        (size_t)256 * 8192, (size_t)8192 * 256);
    k_tcvt<1><<<dim3(256, 8, 4), 256>>>(decy, 256, 8192,
                                        (size_t)256 * 8192, (size_t)8192 * 256);
    k_tcvt<2><<<dim3(8, 1024, 1), 256>>>(enc, 32768, 256, 0, 0);

    for (int l = 0; l < LAYERS; l++) {
        k_mma<0><<<dim3(256, 4), 256, SMEM_BYTES>>>(nullptr);        // x + rope
        k_mma<2><<<dim3(3, 8, SPLITS2), 256, SMEM_BYTES>>>(nullptr); // scores
        k_attn<<<512, 256>>>();                                      // softmax+PV+LN
        k_mma<1><<<dim3(256, 4), 256, SMEM_BYTES>>>(nullptr);        // y hi/lo
        k_mma<3><<<dim3(2, 4, SPLITS3), 256, SMEM_BYTES>>>(nullptr); // enc
        k_residual<<<512, 256>>>();                                  // z-sum + ln+ln
    }

    k_tcvt<3><<<dim3(1000, 8, 1), 256>>>(ro, 256, 32000, 0, 0);      // readout wts
    k_mma<4><<<dim3(250, 4), 256, SMEM_BYTES>>>(out);                // logits
}

// round 17
// speedup vs baseline: 1.0153x; 1.0153x over previous
#include <cuda_runtime.h>
#include <cuda_bf16.h>
#include <math.h>
#include <stdint.h>

// ---------------------------------------------------------------------------
// BDH forward. GEMMs = bf16 hi/lo 3-combo merged-pass HMMA, cp.async 2-stage
// pipeline, 128x128 tiles, wave-balanced split-K grids, fused attention tail,
// vectorized weight transposes, score-diagonal fill dedup, vectorized epilogue.
// B=2,T=256,D=256,H=4,n=8192,N=32768,V=32000,L=6
// ---------------------------------------------------------------------------
#define LAYERS 6
#define LN_EPS 1e-5f
#define SCALE_ATTN 0.011048543456039806f   // 1/sqrt(8192)

#define ROWE 40                  // smem row stride in bf16 elements (80 bytes)
#define TILE_E (128 * ROWE)      // 5120 bf16 per tile
#define BUF_E  (4 * TILE_E)      // 4 tiles per buffer
#define SMEM_BYTES (2 * BUF_E * 2)   // 81920 B

#define SPLITS2 12               // scores split-K (256 chunks -> 21/22 each)
#define SPLITS3 36               // enc split-K (1024 chunks -> 28/29 each)

__device__ __forceinline__ uint32_t smem_u32(const void* p) {
    uint32_t a;
    asm("{ .reg .u64 t; cvta.to.shared.u64 t, %1; cvt.u32.u64 %0, t; }"
        : "=r"(a) : "l"(p));
    return a;
}
#define CP16(dst, src) \
    asm volatile("cp.async.cg.shared.global [%0], [%1], 16;" \
        :: "r"(dst), "l"(src) : "memory")
#define CP_COMMIT() asm volatile("cp.async.commit_group;" ::: "memory")
#define CP_WAIT(n)  asm volatile("cp.async.wait_group %0;" :: "n"(n) : "memory")

__device__ __forceinline__ void mma16816(float d[4], const uint32_t a[4],
                                         uint32_t b0, uint32_t b1) {
    asm volatile(
        "mma.sync.aligned.m16n8k16.row.col.f32.bf16.bf16.f32 "
        "{%0,%1,%2,%3}, {%4,%5,%6,%7}, {%8,%9}, {%0,%1,%2,%3};"
        : "+f"(d[0]), "+f"(d[1]), "+f"(d[2]), "+f"(d[3])
        : "r"(a[0]), "r"(a[1]), "r"(a[2]), "r"(a[3]), "r"(b0), "r"(b1));
}

// ------------------------- device globals ----------------------------------
__device__ float g_v[512*256];
__device__ __align__(16) float g_x[(size_t)8*256*8192];   // (b*4+h, t, i)
__device__ float g_cos[256*4096];
__device__ float g_sin[256*4096];
__device__ __align__(16) float g_sparts[(size_t)SPLITS2*8*256*256];
__device__ __align__(16) float g_kparts[(size_t)SPLITS3*512*256];

__device__ __align__(16) __nv_bfloat16 v_h[512*256],   v_l[512*256];
__device__ __align__(16) __nv_bfloat16 lna_h[512*256], lna_l[512*256];
__device__ __align__(16) __nv_bfloat16 xr_h[(size_t)8*256*8192];
__device__ __align__(16) __nv_bfloat16 xr_l[(size_t)8*256*8192];
__device__ __align__(16) __nv_bfloat16 y_h[(size_t)512*32768];
__device__ __align__(16) __nv_bfloat16 y_l[(size_t)512*32768];
__device__ __align__(16) __nv_bfloat16 dxt_h[(size_t)32768*256];
__device__ __align__(16) __nv_bfloat16 dxt_l[(size_t)32768*256];
__device__ __align__(16) __nv_bfloat16 dyt_h[(size_t)32768*256];
__device__ __align__(16) __nv_bfloat16 dyt_l[(size_t)32768*256];
__device__ __align__(16) __nv_bfloat16 et_h[(size_t)256*32768];
__device__ __align__(16) __nv_bfloat16 et_l[(size_t)256*32768];
__device__ __align__(16) __nv_bfloat16 rt_h[(size_t)32000*256];
__device__ __align__(16) __nv_bfloat16 rt_l[(size_t)32000*256];

__device__ __forceinline__ void bf16split(float v, __nv_bfloat16& h, __nv_bfloat16& l) {
    h = __float2bfloat16(v);
    l = __float2bfloat16(v - __bfloat162float(h));
}

// ------------------------- block reductions --------------------------------
__device__ __forceinline__ float blk_sum256(float v, float* sh) {
#pragma unroll
    for (int o = 16; o > 0; o >>= 1) v += __shfl_xor_sync(0xffffffffu, v, o);
    if ((threadIdx.x & 31) == 0) sh[threadIdx.x >> 5] = v;
    __syncthreads();
    float tot = 0.f;
#pragma unroll
    for (int w = 0; w < 8; w++) tot += sh[w];
    __syncthreads();
    return tot;
}
__device__ __forceinline__ float blk_max256(float v, float* sh) {
#pragma unroll
    for (int o = 16; o > 0; o >>= 1) v = fmaxf(v, __shfl_xor_sync(0xffffffffu, v, o));
    if ((threadIdx.x & 31) == 0) sh[threadIdx.x >> 5] = v;
    __syncthreads();
    float tot = -3.0e38f;
#pragma unroll
    for (int w = 0; w < 8; w++) tot = fmaxf(tot, sh[w]);
    __syncthreads();
    return tot;
}
__device__ __forceinline__ float ln_elem(float x, float* sh) {
    float mean = blk_sum256(x, sh) * (1.f / 256.f);
    float d = x - mean;
    float var = blk_sum256(d * d, sh) * (1.f / 256.f);
    return d * rsqrtf(var + LN_EPS);
}

// ------------------------- small kernels -----------------------------------
__global__ void k_rope_table() {
    int idx = blockIdx.x * 256 + threadIdx.x;
    int i = idx & 4095;
    int t = idx >> 12;
    float ex = (float)(2 * i) * (1.0f / 8192.0f);
    float inv = expf(-9.210340371976184f * ex);
    float f = (float)t * inv;
    float s, c;
    sincosf(f, &s, &c);
    g_cos[idx] = c;
    g_sin[idx] = s;
}

__global__ void k_embed(const int* __restrict__ idx, const float* __restrict__ wte) {
    __shared__ float sh[8];
    int row = blockIdx.x, tid = threadIdx.x;
    int tok = idx[row];
    float x = wte[(size_t)tok * 256 + tid];
    float r = ln_elem(x, sh);
    g_v[row * 256 + tid] = r;
    __nv_bfloat16 h, l; bf16split(r, h, l);
    v_h[row * 256 + tid] = h; v_l[row * 256 + tid] = l;
}

// transpose + bf16 hi/lo: out[c*R + r] = in[r*C + c]; DST selected in-kernel.
template<int DST>
__global__ void k_tcvt(const float* __restrict__ in, int R, int C,
                       size_t in_z, size_t out_z) {
    __shared__ float tile[32][33];
    __nv_bfloat16* oh;
    __nv_bfloat16* ol;
    if (DST == 0) { oh = dxt_h; ol = dxt_l; }
    else if (DST == 1) { oh = dyt_h; ol = dyt_l; }
    else if (DST == 2) { oh = et_h; ol = et_l; }
    else { oh = rt_h; ol = rt_l; }
    int z = blockIdx.z;
    const float* src = in + (size_t)z * in_z;
    __nv_bfloat16* dh = oh + (size_t)z * out_z;
    __nv_bfloat16* dl = ol + (size_t)z * out_z;
    int r0 = blockIdx.y * 32, c0 = blockIdx.x * 32;
    int t = threadIdx.x;
    {
        int row = t >> 3, c4 = (t & 7) << 2;
        float4 v = *reinterpret_cast<const float4*>(
            src + (size_t)(r0 + row) * C + c0 + c4);
        tile[row][c4 + 0] = v.x; tile[row][c4 + 1] = v.y;
        tile[row][c4 + 2] = v.z; tile[row][c4 + 3] = v.w;
    }
    __syncthreads();
    {
        int ci = t >> 3, rp = (t & 7) << 2;
        float f0 = tile[rp + 0][ci], f1 = tile[rp + 1][ci];
        float f2 = tile[rp + 2][ci], f3 = tile[rp + 3][ci];
        __nv_bfloat16 h0, l0, h1, l1, h2, l2, h3, l3;
        bf16split(f0, h0, l0); bf16split(f1, h1, l1);
        bf16split(f2, h2, l2); bf16split(f3, h3, l3);
        size_t o = (size_t)(c0 + ci) * R + r0 + rp;
        *reinterpret_cast<__nv_bfloat162*>(&dh[o])     = __nv_bfloat162(h0, h1);
        *reinterpret_cast<__nv_bfloat162*>(&dh[o + 2]) = __nv_bfloat162(h2, h3);
        *reinterpret_cast<__nv_bfloat162*>(&dl[o])     = __nv_bfloat162(l0, l1);
        *reinterpret_cast<__nv_bfloat162*>(&dl[o + 2]) = __nv_bfloat162(l2, l3);
    }
}

// fused attention tail: softmax (mean over heads) + P@V + LN -> lna hi/lo
__global__ void k_attn() {
    __shared__ float sh[8];
    __shared__ float p[256];
    int row = blockIdx.x;
    int b = row >> 8, t = row & 255;
    int s = threadIdx.x;
    float pacc = 0.f;
    for (int h = 0; h < 4; h++) {
        float val = -3.0e38f;
        if (s <= t) {
            float sum = 0.f;
            int bh = b * 4 + h;
#pragma unroll
            for (int sp = 0; sp < SPLITS2; sp++)
                sum += g_sparts[(((size_t)sp * 8 + bh) * 256 + t) * 256 + s];
            val = sum * SCALE_ATTN;
        }
        float mx = blk_max256(val, sh);
        float e = (s <= t) ? expf(val - mx) : 0.f;
        float ssum = blk_sum256(e, sh);
        pacc += e / ssum;
    }
    p[s] = pacc * 0.25f;
    __syncthreads();
    const float* vb = g_v + (size_t)b * 65536;
    float a = 0.f;
#pragma unroll 8
    for (int s2 = 0; s2 < 256; s2++)
        a = fmaf(p[s2], vb[s2 * 256 + s], a);
    float r = ln_elem(a, sh);
    __nv_bfloat16 h, l; bf16split(r, h, l);
    lna_h[row * 256 + s] = h; lna_l[row * 256 + s] = l;
}

// fused: z = sum of SPLITS3 split-K partials; v = ln(v + ln(z))
__global__ void k_residual() {
    __shared__ float sh[8];
    int row = blockIdx.x, tid = threadIdx.x;
    int i = row * 256 + tid;
    float z = 0.f;
#pragma unroll
    for (int sp = 0; sp < SPLITS3; sp++) z += g_kparts[(size_t)sp * 131072 + i];
    float lnz = ln_elem(z, sh);
    float t = g_v[i] + lnz;
    float r = ln_elem(t, sh);
    g_v[i] = r;
    __nv_bfloat16 h, l; bf16split(r, h, l);
    v_h[i] = h; v_l[i] = l;
}

// ------------------------- HMMA GEMM (merged, cp.async 2-stage) -------------
// MODE: 0=dec-x (relu -> g_x + fused rope -> xr hi/lo)
//       1=dec-y (relu * g_x -> y hi/lo)
//       2=scores (fp32 -> g_sparts, 12 uneven splits; diag tiles reuse A fills)
//       3=enc (fp32 -> g_kparts, 36 uneven splits)   4=readout (fp32 -> out)
// 128x128 tile, BK=32 (2 k-steps), 8 warps (2m x 4n), warp tile 64x32.
// Per chunk: Ah,Al,Bh,Bl tiles via cp.async; cfr += Ah*Bh + Ah*Bl + Al*Bh.
template<int MODE>
__global__ void __launch_bounds__(256, 2) k_mma(float* __restrict__ outp) {
    extern __shared__ __align__(16) __nv_bfloat16 smem_dyn[];
    const uint32_t sbase = smem_u32(smem_dyn);

    int tid = threadIdx.x;
    int wid = tid >> 5, lane = tid & 31;
    int warp_m = wid & 1, warp_n = wid >> 1;
    int gid = lane >> 2, tig = lane & 3;

    const __nv_bfloat16 *Ah, *Al, *Bh, *Bl;
    size_t K;
    int m0, n0, k0, total;
    if (MODE == 0) {
        Ah = v_h; Al = v_l; Bh = dxt_h; Bl = dxt_l;
        K = 256; m0 = blockIdx.y << 7; n0 = blockIdx.x << 7; k0 = 0; total = 8;
    } else if (MODE == 1) {
        Ah = lna_h; Al = lna_l; Bh = dyt_h; Bl = dyt_l;
        K = 256; m0 = blockIdx.y << 7; n0 = blockIdx.x << 7; k0 = 0; total = 8;
    } else if (MODE == 2) {
        size_t off = (size_t)blockIdx.y * 256 * 8192;
        Ah = xr_h + off; Al = xr_l + off; Bh = Ah; Bl = Al;
        K = 8192;
        int tp = blockIdx.x;
        m0 = ((tp + 1) >> 1) << 7; n0 = (tp >> 1) << 7;
        int s = blockIdx.z;                         // 12 uneven splits of 256 chunks
        total = 21 + (s < 4);
        k0 = (21 * s + min(s, 4)) << 5;
    } else if (MODE == 3) {
        Ah = y_h; Al = y_l; Bh = et_h; Bl = et_l;
        K = 32768; m0 = blockIdx.y << 7; n0 = blockIdx.x << 7;
        int s = blockIdx.z;                         // 36 uneven splits of 1024 chunks
        total = 28 + (s < 16);
        k0 = (28 * s + min(s, 16)) << 5;
    } else {
        Ah = v_h; Al = v_l; Bh = rt_h; Bl = rt_l;
        K = 256; m0 = blockIdx.y << 7; n0 = blockIdx.x << 7; k0 = 0; total = 8;
    }

    // score diagonal tiles: B data == A data; skip B fills, alias smem
    const bool diag = (MODE == 2) && (m0 == n0);

    // per-thread fill geometry: rows r and r+64, 16B column chunk c16
    const int r = tid >> 2, c16 = tid & 3;
    const uint32_t dOff0 = (uint32_t)(r * ROWE + c16 * 8) * 2;          // bytes
    const uint32_t dOff1 = (uint32_t)((r + 64) * ROWE + c16 * 8) * 2;

#define CPA_CHUNK(c) do {                                                     \
        int _kk = k0 + ((c) << 5);                                            \
        uint32_t _b = sbase + ((c) & 1) * (BUF_E * 2);                        \
        const size_t _ao0 = (size_t)(m0 + r) * K + _kk + c16 * 8;            \
        const size_t _ao1 = (size_t)(m0 + r + 64) * K + _kk + c16 * 8;       \
        CP16(_b + dOff0, Ah + _ao0);                                          \
        CP16(_b + dOff1, Ah + _ao1);                                          \
        CP16(_b + TILE_E * 2 + dOff0, Al + _ao0);                             \
        CP16(_b + TILE_E * 2 + dOff1, Al + _ao1);                             \
        if (!diag) {                                                          \
            const size_t _bo0 = (size_t)(n0 + r) * K + _kk + c16 * 8;        \
            const size_t _bo1 = (size_t)(n0 + r + 64) * K + _kk + c16 * 8;   \
            CP16(_b + TILE_E * 4 + dOff0, Bh + _bo0);                         \
            CP16(_b + TILE_E * 4 + dOff1, Bh + _bo1);                         \
            CP16(_b + TILE_E * 6 + dOff0, Bl + _bo0);                         \
            CP16(_b + TILE_E * 6 + dOff1, Bl + _bo1);                         \
        }                                                                     \
    } while (0)

    float cfr[4][4][4] = {};            // [mi][ng][reg]

    CPA_CHUNK(0); CP_COMMIT();
    if (total > 1) { CPA_CHUNK(1); CP_COMMIT(); }

    for (int c = 0; c < total; c++) {
        if (c + 1 < total) CP_WAIT(1); else CP_WAIT(0);
        __syncthreads();

        const __nv_bfloat16* sAh = smem_dyn + (c & 1) * BUF_E;
        const __nv_bfloat16* sAl = sAh + TILE_E;
        const __nv_bfloat16* sBh = diag ? sAh : (sAl + TILE_E);
        const __nv_bfloat16* sBl = diag ? sAl : (sAl + 2 * TILE_E);
#pragma unroll
        for (int ks = 0; ks < 2; ks++) {
            const int kc = ks * 16 + tig * 2;
            uint32_t af[4][4];
            uint32_t b0[4], b1[4];
            // --- A-hi fragments ---
#pragma unroll
            for (int mi = 0; mi < 4; mi++) {
                int ar = warp_m * 64 + mi * 16 + gid;
                af[mi][0] = *reinterpret_cast<const uint32_t*>(&sAh[ar * ROWE + kc]);
                af[mi][1] = *reinterpret_cast<const uint32_t*>(&sAh[(ar + 8) * ROWE + kc]);
                af[mi][2] = *reinterpret_cast<const uint32_t*>(&sAh[ar * ROWE + kc + 8]);
                af[mi][3] = *reinterpret_cast<const uint32_t*>(&sAh[(ar + 8) * ROWE + kc + 8]);
            }
            // --- combo hi*hi ---
#pragma unroll
            for (int ng = 0; ng < 4; ng++) {
                int br = warp_n * 32 + ng * 8 + gid;
                b0[ng] = *reinterpret_cast<const uint32_t*>(&sBh[br * ROWE + kc]);
                b1[ng] = *reinterpret_cast<const uint32_t*>(&sBh[br * ROWE + kc + 8]);
            }
#pragma unroll
            for (int mi = 0; mi < 4; mi++)
#pragma unroll
                for (int ng = 0; ng < 4; ng++)
                    mma16816(cfr[mi][ng], af[mi], b0[ng], b1[ng]);
            // --- combo hi*lo ---
#pragma unroll
            for (int ng = 0; ng < 4; ng++) {
                int br = warp_n * 32 + ng * 8 + gid;
                b0[ng] = *reinterpret_cast<const uint32_t*>(&sBl[br * ROWE + kc]);
                b1[ng] = *reinterpret_cast<const uint32_t*>(&sBl[br * ROWE + kc + 8]);
            }
#pragma unroll
            for (int mi = 0; mi < 4; mi++)
#pragma unroll
                for (int ng = 0; ng < 4; ng++)
                    mma16816(cfr[mi][ng], af[mi], b0[ng], b1[ng]);
            // --- combo lo*hi ---
#pragma unroll
            for (int mi = 0; mi < 4; mi++) {
                int ar = warp_m * 64 + mi * 16 + gid;
                af[mi][0] = *reinterpret_cast<const uint32_t*>(&sAl[ar * ROWE + kc]);
                af[mi][1] = *reinterpret_cast<const uint32_t*>(&sAl[(ar + 8) * ROWE + kc]);
                af[mi][2] = *reinterpret_cast<const uint32_t*>(&sAl[ar * ROWE + kc + 8]);
                af[mi][3] = *reinterpret_cast<const uint32_t*>(&sAl[(ar + 8) * ROWE + kc + 8]);
            }
#pragma unroll
            for (int ng = 0; ng < 4; ng++) {
                int br = warp_n * 32 + ng * 8 + gid;
                b0[ng] = *reinterpret_cast<const uint32_t*>(&sBh[br * ROWE + kc]);
                b1[ng] = *reinterpret_cast<const uint32_t*>(&sBh[br * ROWE + kc + 8]);
            }
#pragma unroll
            for (int mi = 0; mi < 4; mi++)
#pragma unroll
                for (int ng = 0; ng < 4; ng++)
                    mma16816(cfr[mi][ng], af[mi], b0[ng], b1[ng]);
        }
        __syncthreads();                 // all warps done with buf (c&1)
        if (c + 2 < total) { CPA_CHUNK(c + 2); CP_COMMIT(); }
    }
#undef CPA_CHUNK

    // ---- epilogue (vectorized stores) ----
#pragma unroll
    for (int mi = 0; mi < 4; mi++) {
#pragma unroll
        for (int hh = 0; hh < 2; hh++) {
            int row = m0 + warp_m * 64 + mi * 16 + gid + hh * 8;
#pragma unroll
            for (int ng = 0; ng < 4; ng++) {
                int col = n0 + warp_n * 32 + ng * 8 + tig * 2;
                float v0 = cfr[mi][ng][hh * 2 + 0];
                float v1 = cfr[mi][ng][hh * 2 + 1];
                if (MODE == 0) {
                    int b = row >> 8, t = row & 255;
                    int hd = col >> 13, i = col & 8191;
                    size_t xi = ((size_t)((b << 2) + hd) * 256 + t) * 8192 + i;
                    float xe = fmaxf(v0, 0.f), xo = fmaxf(v1, 0.f);
                    *reinterpret_cast<float2*>(&g_x[xi]) = make_float2(xe, xo);
                    int ci = t * 4096 + (i >> 1);
                    float cc = g_cos[ci], ss = g_sin[ci];
                    float re = xe * cc - xo * ss;
                    float ro = xo * cc + xe * ss;
                    __nv_bfloat16 h0, l0, h1, l1;
                    bf16split(re, h0, l0); bf16split(ro, h1, l1);
                    *reinterpret_cast<__nv_bfloat162*>(&xr_h[xi]) = __nv_bfloat162(h0, h1);
                    *reinterpret_cast<__nv_bfloat162*>(&xr_l[xi]) = __nv_bfloat162(l0, l1);
                } else if (MODE == 1) {
                    int b = row >> 8, t = row & 255;
                    int hd = col >> 13, i = col & 8191;
                    size_t xi = ((size_t)((b << 2) + hd) * 256 + t) * 8192 + i;
                    float2 xv = *reinterpret_cast<const float2*>(&g_x[xi]);
                    float y0 = fmaxf(v0, 0.f) * xv.x;
                    float y1 = fmaxf(v1, 0.f) * xv.y;
                    size_t yi = (size_t)row * 32768 + col;
                    __nv_bfloat16 h0, l0, h1, l1;
                    bf16split(y0, h0, l0); bf16split(y1, h1, l1);
                    *reinterpret_cast<__nv_bfloat162*>(&y_h[yi]) = __nv_bfloat162(h0, h1);
                    *reinterpret_cast<__nv_bfloat162*>(&y_l[yi]) = __nv_bfloat162(l0, l1);
                } else if (MODE == 2) {
                    size_t ob = (((size_t)blockIdx.z * 8 + blockIdx.y) * 256 + row) * 256 + col;
                    *reinterpret_cast<float2*>(&g_sparts[ob]) = make_float2(v0, v1);
                } else if (MODE == 3) {
                    size_t ob = ((size_t)blockIdx.z * 512 + row) * 256 + col;
                    *reinterpret_cast<float2*>(&g_kparts[ob]) = make_float2(v0, v1);
                } else {
                    size_t ob = (size_t)row * 32000 + col;
                    *reinterpret_cast<float2*>(&outp[ob]) = make_float2(v0, v1);
                }
            }
        }
    }
}

// ------------------------- host launcher -----------------------------------
extern "C" void kernel_launch(void* const* d_in, const int* in_sizes, int n_in,
                              void* d_out, int out_size) {
    const int*   idx  = (const int*)d_in[0];
    const float* wte  = (const float*)d_in[1];
    const float* enc  = (const float*)d_in[2];
    const float* decx = (const float*)d_in[3];
    const float* decy = (const float*)d_in[4];
    const float* ro   = (const float*)d_in[5];
    float* out = (float*)d_out;
    (void)in_sizes; (void)n_in; (void)out_size;

    cudaFuncSetAttribute(k_mma<0>, cudaFuncAttributeMaxDynamicSharedMemorySize, SMEM_BYTES);
    cudaFuncSetAttribute(k_mma<1>, cudaFuncAttributeMaxDynamicSharedMemorySize, SMEM_BYTES);
    cudaFuncSetAttribute(k_mma<2>, cudaFuncAttributeMaxDynamicSharedMemorySize, SMEM_BYTES);
    cudaFuncSetAttribute(k_mma<3>, cudaFuncAttributeMaxDynamicSharedMemorySize, SMEM_BYTES);
    cudaFuncSetAttribute(k_mma<4>, cudaFuncAttributeMaxDynamicSharedMemorySize, SMEM_BYTES);

    k_rope_table<<<4096, 256>>>();
    k_embed<<<512, 256>>>(idx, wte);
    k_tcvt<0><<<dim3(256, 8, 4), 256>>>(decx, 256, 8192,
                                        (size_t)256 * 8192, (size_t)8192 * 256);
    k_tcvt<1><<<dim3(256, 8, 4), 256>>>(decy, 256, 8192,
                                        (size_t)256 * 8192, (size_t)8192 * 256);
    k_tcvt<2><<<dim3(8, 1024, 1), 256>>>(enc, 32768, 256, 0, 0);

    for (int l = 0; l < LAYERS; l++) {
        k_mma<0><<<dim3(256, 4), 256, SMEM_BYTES>>>(nullptr);        // x + rope
        k_mma<2><<<dim3(3, 8, SPLITS2), 256, SMEM_BYTES>>>(nullptr); // scores
        k_attn<<<512, 256>>>();                                      // softmax+PV+LN
        k_mma<1><<<dim3(256, 4), 256, SMEM_BYTES>>>(nullptr);        // y hi/lo
        k_mma<3><<<dim3(2, 4, SPLITS3), 256, SMEM_BYTES>>>(nullptr); // enc
        k_residual<<<512, 256>>>();                                  // z-sum + ln+ln
    }

    k_tcvt<3><<<dim3(1000, 8, 1), 256>>>(ro, 256, 32000, 0, 0);      // readout wts
    k_mma<4><<<dim3(250, 4), 256, SMEM_BYTES>>>(out);                // logits
}